// round 4
// baseline (speedup 1.0000x reference)
#include <cuda_runtime.h>
#include <cuda_bf16.h>
#include <cstdint>

// ============================================================================
// xFuserMXFP4Linear: fake-MXFP4 (e2m1 + E8M0 per-1x32-block scale) quant of
// A[M,K] and W[N,K], then fp32 GEMM out = Aq @ Wq^T + bias.
//
// NOTE: this toolchain emits PTX for target sm_103 (no 'a'), so tcgen05/TMA
// are unavailable. We use the baseline-PTX tensor path instead:
// cp.async + ldmatrix + mma.sync.m16n8k16 (bf16 in, fp32 accum).
// All dequantized MXFP4 values are exactly representable in bf16, so the
// bf16 MMA with fp32 accumulation reproduces the reference exactly
// (modulo fp32 accumulation order).
// ============================================================================

// ---------------- device scratch (allowed: __device__ globals) --------------
__device__ __nv_bfloat16 g_Aq[8192u * 2048u];   // 32 MB
__device__ __nv_bfloat16 g_Wq[2048u * 2048u];   // 8 MB

// ============================================================================
// PTX helpers (baseline ISA only — valid on plain sm_103 target)
// ============================================================================
__device__ __forceinline__ uint32_t smem_to_u32(const void* smem_ptr) {
    uint32_t addr;
    asm("{ .reg .u64 tmp; cvta.to.shared.u64 tmp, %1; cvt.u32.u64 %0, tmp; }"
        : "=r"(addr) : "l"(smem_ptr));
    return addr;
}

#define CP_ASYNC16(smem_u32, gptr) \
    asm volatile("cp.async.cg.shared.global [%0], [%1], 16;\n" \
                 :: "r"(smem_u32), "l"(gptr))

#define CP_COMMIT() asm volatile("cp.async.commit_group;\n" ::: "memory")
#define CP_WAIT(n)  asm volatile("cp.async.wait_group %0;\n" :: "n"(n) : "memory")

__device__ __forceinline__ void ldsm_x4(uint32_t* r, uint32_t addr) {
    asm volatile("ldmatrix.sync.aligned.m8n8.x4.shared.b16 {%0,%1,%2,%3}, [%4];"
                 : "=r"(r[0]), "=r"(r[1]), "=r"(r[2]), "=r"(r[3]) : "r"(addr));
}

__device__ __forceinline__ void mma_16816(float* c, const uint32_t* a,
                                          const uint32_t* b) {
    asm volatile(
        "mma.sync.aligned.m16n8k16.row.col.f32.bf16.bf16.f32 "
        "{%0,%1,%2,%3}, {%4,%5,%6,%7}, {%8,%9}, {%0,%1,%2,%3};"
        : "+f"(c[0]), "+f"(c[1]), "+f"(c[2]), "+f"(c[3])
        : "r"(a[0]), "r"(a[1]), "r"(a[2]), "r"(a[3]), "r"(b[0]), "r"(b[1]));
}

// ============================================================================
// Quantize kernel: one thread handles one 1x32 block along K.
// Exactly replicates the reference math; exp via frexpf (exact floor(log2)).
// ============================================================================
__global__ void __launch_bounds__(256) quant_mxfp4_kernel(
    const float* __restrict__ x, __nv_bfloat16* __restrict__ out, int nblocks)
{
    int b = blockIdx.x * blockDim.x + threadIdx.x;
    if (b >= nblocks) return;

    const float4* src = reinterpret_cast<const float4*>(x + (size_t)b * 32);
    float4 v[8];
    float amax = 0.f;
#pragma unroll
    for (int i = 0; i < 8; i++) {
        v[i] = src[i];
        amax = fmaxf(amax, fmaxf(fmaxf(fabsf(v[i].x), fabsf(v[i].y)),
                                 fmaxf(fabsf(v[i].z), fabsf(v[i].w))));
    }

    float scale = 1.f, inv = 1.f;
    bool use_inv = true;
    if (amax > 0.f) {
        int e;
        frexpf(fmaxf(amax, 1.17549435e-38f), &e);   // amax = m*2^e, m in [0.5,1)
        // floor(log2(amax)) = e-1 ; scale = 2^(e-1-2)
        scale = ldexpf(1.f, e - 3);
        use_inv = (e >= -120);                      // 2^(3-e) representable
        inv = use_inv ? ldexpf(1.f, 3 - e) : 1.f;
    }

    __nv_bfloat16 q[32];
#pragma unroll
    for (int i = 0; i < 8; i++) {
        float in4[4] = {v[i].x, v[i].y, v[i].z, v[i].w};
#pragma unroll
        for (int j = 0; j < 4; j++) {
            float qv = use_inv ? in4[j] * inv : in4[j] / scale;
            qv = fminf(fmaxf(qv, -6.f), 6.f);
            float aq = fabsf(qv);
            // e2m1 ulp: 0.5 on [0,2), 1 on [2,4), 2 on [4,6]
            float lsb  = aq < 2.f ? 0.5f : (aq < 4.f ? 1.f : 2.f);
            float rlsb = aq < 2.f ? 2.f  : (aq < 4.f ? 1.f : 0.5f);
            float qr = rintf(qv * rlsb) * lsb;      // RNE onto fp4 grid (exact arith)
            q[i * 4 + j] = __float2bfloat16(qr * scale);  // exact in bf16
        }
    }

    uint4* dst = reinterpret_cast<uint4*>(out + (size_t)b * 32);
    const uint4* qs = reinterpret_cast<const uint4*>(q);
#pragma unroll
    for (int i = 0; i < 4; i++) dst[i] = qs[i];
}

// ============================================================================
// bf16 GEMM via mma.sync: out[M,N] = Aq[M,K] @ Wq[N,K]^T + bias
// CTA tile 128x128x32, 256 threads (8 warps, 4x2), warp tile 32x64.
// Double-buffered cp.async pipeline. Smem rows padded to 80B (20-bank shift
// per row -> conflict-free ldmatrix).
// ============================================================================
static constexpr int BM = 128;
static constexpr int BN = 128;
static constexpr int BK = 32;            // bf16 elems per K-stage
static constexpr int ROW_H = 40;         // smem row stride in halves (80 B)
static constexpr int TILE_H = 128 * ROW_H;            // halves per tile buffer
static constexpr int TILE_B = TILE_H * 2;             // bytes  (10240)
static constexpr int SMEM_TOTAL = 4 * TILE_B;         // A0 A1 B0 B1 = 40 KB

__global__ void __launch_bounds__(256) mxfp4_gemm_kernel(
    const __nv_bfloat16* __restrict__ A,   // [M,K]
    const __nv_bfloat16* __restrict__ W,   // [N,K]
    const float* __restrict__ bias,        // [N]
    float* __restrict__ out,               // [M,N]
    int M, int N, int K)
{
    extern __shared__ __align__(16) char smem[];
    const uint32_t sb = smem_to_u32(smem);
    const uint32_t sA[2] = { sb,              sb + TILE_B };
    const uint32_t sB[2] = { sb + 2 * TILE_B, sb + 3 * TILE_B };

    const int tid = threadIdx.x;
    const int wid = tid >> 5;
    const int lid = tid & 31;
    const int warp_m = wid >> 1;          // 0..3
    const int warp_n = wid & 1;           // 0..1
    const int m0 = blockIdx.y * BM;
    const int n0 = blockIdx.x * BN;

    // cp.async mapping: 512 16B-chunks per tile, 2 per thread
    const int ldr0 = tid;                 // chunk indices tid, tid+256
    const int ldr1 = tid + 256;
    const int r0 = ldr0 >> 2, c0 = ldr0 & 3;
    const int r1 = ldr1 >> 2, c1 = ldr1 & 3;

    const __nv_bfloat16* Abase = A + (size_t)m0 * K;
    const __nv_bfloat16* Wbase = W + (size_t)n0 * K;

    auto prefetch = [&](int stage, int kk) {
        CP_ASYNC16(sA[stage] + (uint32_t)(r0 * ROW_H + c0 * 8) * 2,
                   Abase + (size_t)r0 * K + kk + c0 * 8);
        CP_ASYNC16(sA[stage] + (uint32_t)(r1 * ROW_H + c1 * 8) * 2,
                   Abase + (size_t)r1 * K + kk + c1 * 8);
        CP_ASYNC16(sB[stage] + (uint32_t)(r0 * ROW_H + c0 * 8) * 2,
                   Wbase + (size_t)r0 * K + kk + c0 * 8);
        CP_ASYNC16(sB[stage] + (uint32_t)(r1 * ROW_H + c1 * 8) * 2,
                   Wbase + (size_t)r1 * K + kk + c1 * 8);
    };

    float acc[2][8][4];
#pragma unroll
    for (int tm = 0; tm < 2; tm++)
#pragma unroll
        for (int nt = 0; nt < 8; nt++)
#pragma unroll
            for (int j = 0; j < 4; j++) acc[tm][nt][j] = 0.f;

    // ldmatrix lane address components (fixed per thread)
    const int aRowBase = warp_m * 32;     // + tm*16 + (lid&15)
    const int bRowBase = warp_n * 64;     // + ntp*16 + pair rows

    const int nK = K / BK;

    prefetch(0, 0);
    CP_COMMIT();

    for (int kt = 0; kt < nK; kt++) {
        const int cur = kt & 1;
        const int nxt = cur ^ 1;
        if (kt + 1 < nK) prefetch(nxt, (kt + 1) * BK);
        CP_COMMIT();
        CP_WAIT(1);
        __syncthreads();

        // ---- load fragments ----
        uint32_t af[2][2][4];   // [ks][tm][4]
        uint32_t bf[2][8][2];   // [ks][nt][2]
#pragma unroll
        for (int ks = 0; ks < 2; ks++) {
#pragma unroll
            for (int tm = 0; tm < 2; tm++) {
                int row = aRowBase + tm * 16 + (lid & 15);
                int col = ks * 16 + (lid >> 4) * 8;
                ldsm_x4(af[ks][tm], sA[cur] + (uint32_t)(row * ROW_H + col) * 2);
            }
#pragma unroll
            for (int ntp = 0; ntp < 4; ntp++) {
                int g = lid >> 3;
                int row = bRowBase + ntp * 16 + (g >> 1) * 8 + (lid & 7);
                int col = ks * 16 + (g & 1) * 8;
                uint32_t r[4];
                ldsm_x4(r, sB[cur] + (uint32_t)(row * ROW_H + col) * 2);
                bf[ks][2 * ntp][0]     = r[0];
                bf[ks][2 * ntp][1]     = r[1];
                bf[ks][2 * ntp + 1][0] = r[2];
                bf[ks][2 * ntp + 1][1] = r[3];
            }
        }

        // ---- 32 mma per warp per stage ----
#pragma unroll
        for (int ks = 0; ks < 2; ks++)
#pragma unroll
            for (int tm = 0; tm < 2; tm++)
#pragma unroll
                for (int nt = 0; nt < 8; nt++)
                    mma_16816(acc[tm][nt], af[ks][tm], bf[ks][nt]);

        __syncthreads();
    }

    // ---- epilogue: fused bias, float2 stores ----
    const int g = lid >> 2;               // 0..7
    const int tc = (lid & 3) * 2;         // 0,2,4,6
#pragma unroll
    for (int nt = 0; nt < 8; nt++) {
        int col = n0 + warp_n * 64 + nt * 8 + tc;
        float2 bv = *reinterpret_cast<const float2*>(bias + col);
#pragma unroll
        for (int tm = 0; tm < 2; tm++) {
            int row = m0 + warp_m * 32 + tm * 16 + g;
            float2 v0 = { acc[tm][nt][0] + bv.x, acc[tm][nt][1] + bv.y };
            float2 v1 = { acc[tm][nt][2] + bv.x, acc[tm][nt][3] + bv.y };
            *reinterpret_cast<float2*>(out + (size_t)row * N + col) = v0;
            *reinterpret_cast<float2*>(out + (size_t)(row + 8) * N + col) = v1;
        }
    }
}

// ============================================================================
// launch
// ============================================================================
extern "C" void kernel_launch(void* const* d_in, const int* in_sizes, int n_in,
                              void* d_out, int out_size)
{
    const float* inp  = (const float*)d_in[0];   // [B*S, K] fp32
    const float* w    = (const float*)d_in[1];   // [N, K]  fp32
    const float* bias = (const float*)d_in[2];   // [N]     fp32
    float* out = (float*)d_out;

    int N = in_sizes[2];
    int K = in_sizes[1] / N;
    int M = (int)((long long)in_sizes[0] / K);

    __nv_bfloat16 *Aq, *Wq;
    cudaGetSymbolAddress((void**)&Aq, g_Aq);
    cudaGetSymbolAddress((void**)&Wq, g_Wq);

    int ablocks = (int)((long long)M * K / 32);
    int wblocks = (int)((long long)N * K / 32);
    quant_mxfp4_kernel<<<(ablocks + 255) / 256, 256>>>(inp, Aq, ablocks);
    quant_mxfp4_kernel<<<(wblocks + 255) / 256, 256>>>(w, Wq, wblocks);

    dim3 grid(N / BN, M / BM);
    mxfp4_gemm_kernel<<<grid, 256, SMEM_TOTAL>>>(Aq, Wq, bias, out, M, N, K);
}

// round 6
// speedup vs baseline: 1.0970x; 1.0970x over previous
#include <cuda_runtime.h>
#include <cuda_bf16.h>
#include <cstdint>

// ============================================================================
// xFuserMXFP4Linear: fake-MXFP4 (e2m1 + E8M0 per-1x32-block scale) quant of
// A[M,K] and W[N,K], then fp32 GEMM out = Aq @ Wq^T + bias.
//
// Toolchain emits PTX for plain sm_103 => no tcgen05/TMA. Baseline tensor
// path: cp.async + ldmatrix + mma.sync.m16n8k16 (bf16 in, fp32 accum).
// Dequantized MXFP4 values are exact in bf16 => rel_err ~0.
// ============================================================================

// ---------------- device scratch (allowed: __device__ globals) --------------
__device__ __nv_bfloat16 g_Aq[8192u * 2048u];   // 32 MB
__device__ __nv_bfloat16 g_Wq[2048u * 2048u];   // 8 MB

// ============================================================================
// PTX helpers (baseline ISA only)
// ============================================================================
__device__ __forceinline__ uint32_t smem_to_u32(const void* smem_ptr) {
    uint32_t addr;
    asm("{ .reg .u64 tmp; cvta.to.shared.u64 tmp, %1; cvt.u32.u64 %0, tmp; }"
        : "=r"(addr) : "l"(smem_ptr));
    return addr;
}

#define CP_ASYNC16(smem_u32, gptr) \
    asm volatile("cp.async.cg.shared.global [%0], [%1], 16;\n" \
                 :: "r"(smem_u32), "l"(gptr))

#define CP_COMMIT() asm volatile("cp.async.commit_group;\n" ::: "memory")
#define CP_WAIT(n)  asm volatile("cp.async.wait_group %0;\n" :: "n"(n) : "memory")

__device__ __forceinline__ void ldsm_x4(uint32_t* r, uint32_t addr) {
    asm volatile("ldmatrix.sync.aligned.m8n8.x4.shared.b16 {%0,%1,%2,%3}, [%4];"
                 : "=r"(r[0]), "=r"(r[1]), "=r"(r[2]), "=r"(r[3]) : "r"(addr));
}

__device__ __forceinline__ void mma_16816(float* c, const uint32_t* a,
                                          const uint32_t* b) {
    asm volatile(
        "mma.sync.aligned.m16n8k16.row.col.f32.bf16.bf16.f32 "
        "{%0,%1,%2,%3}, {%4,%5,%6,%7}, {%8,%9}, {%0,%1,%2,%3};"
        : "+f"(c[0]), "+f"(c[1]), "+f"(c[2]), "+f"(c[3])
        : "r"(a[0]), "r"(a[1]), "r"(a[2]), "r"(a[3]), "r"(b[0]), "r"(b[1]));
}

// ============================================================================
// Quantize kernel: 8 threads per 1x32 block (each thread owns 4 elems).
// Coalesced float4 loads / 8B stores; amax via 3x shfl.bfly within the
// lane-aligned 8-thread group. Exact reference math (frexpf/ldexpf/rintf).
// ============================================================================
__global__ void __launch_bounds__(256) quant_mxfp4_kernel(
    const float* __restrict__ x, __nv_bfloat16* __restrict__ out, int nquads)
{
    int t = blockIdx.x * blockDim.x + threadIdx.x;   // one float4 per thread
    if (t >= nquads) return;

    float4 v = reinterpret_cast<const float4*>(x)[t];
    float amax = fmaxf(fmaxf(fabsf(v.x), fabsf(v.y)),
                       fmaxf(fabsf(v.z), fabsf(v.w)));
    // reduce across the 8 lanes of this 1x32 block (lane-aligned group)
    amax = fmaxf(amax, __shfl_xor_sync(0xFFFFFFFFu, amax, 1));
    amax = fmaxf(amax, __shfl_xor_sync(0xFFFFFFFFu, amax, 2));
    amax = fmaxf(amax, __shfl_xor_sync(0xFFFFFFFFu, amax, 4));

    float scale = 1.f, inv = 1.f;
    bool use_inv = true;
    if (amax > 0.f) {
        int e;
        frexpf(fmaxf(amax, 1.17549435e-38f), &e);   // amax = m*2^e, m in [0.5,1)
        scale = ldexpf(1.f, e - 3);                 // 2^(floor(log2 amax) - 2)
        use_inv = (e >= -120);
        inv = use_inv ? ldexpf(1.f, 3 - e) : 1.f;
    }

    float in4[4] = {v.x, v.y, v.z, v.w};
    __nv_bfloat16 q[4];
#pragma unroll
    for (int j = 0; j < 4; j++) {
        float qv = use_inv ? in4[j] * inv : in4[j] / scale;
        qv = fminf(fmaxf(qv, -6.f), 6.f);
        float aq = fabsf(qv);
        // e2m1 ulp: 0.5 on [0,2), 1 on [2,4), 2 on [4,6]
        float lsb  = aq < 2.f ? 0.5f : (aq < 4.f ? 1.f : 2.f);
        float rlsb = aq < 2.f ? 2.f  : (aq < 4.f ? 1.f : 0.5f);
        float qr = rintf(qv * rlsb) * lsb;          // RNE onto fp4 grid (exact)
        q[j] = __float2bfloat16(qr * scale);        // exact in bf16
    }
    reinterpret_cast<uint2*>(out)[t] = *reinterpret_cast<const uint2*>(q);
}

// ============================================================================
// bf16 GEMM via mma.sync: out[M,N] = Aq[M,K] @ Wq[N,K]^T + bias
// CTA tile 128x128x32, 256 threads (8 warps, 4x2), warp tile 32x64.
// 3-stage cp.async ring, ONE __syncthreads per K-step, prefetch issued
// immediately after the barrier. Smem rows padded to 80B (conflict-free
// ldmatrix).
// ============================================================================
static constexpr int BM = 128;
static constexpr int BN = 128;
static constexpr int BK = 32;            // bf16 elems per K-stage
static constexpr int STAGES = 3;
static constexpr int ROW_H = 40;         // smem row stride in halves (80 B)
static constexpr int TILE_B = 128 * ROW_H * 2;        // 10240 bytes per tile
static constexpr int STAGE_B = 2 * TILE_B;            // A + B per stage
static constexpr int SMEM_TOTAL = STAGES * STAGE_B;   // 61440 bytes

__global__ void __launch_bounds__(256) mxfp4_gemm_kernel(
    const __nv_bfloat16* __restrict__ A,   // [M,K]
    const __nv_bfloat16* __restrict__ W,   // [N,K]
    const float* __restrict__ bias,        // [N]
    float* __restrict__ out,               // [M,N]
    int M, int N, int K)
{
    extern __shared__ __align__(16) char smem[];
    const uint32_t sb = smem_to_u32(smem);

    const int tid = threadIdx.x;
    const int wid = tid >> 5;
    const int lid = tid & 31;
    const int warp_m = wid >> 1;          // 0..3
    const int warp_n = wid & 1;           // 0..1
    const int m0 = blockIdx.y * BM;
    const int n0 = blockIdx.x * BN;

    // cp.async mapping: 512 16B-chunks per tile, 2 per thread
    const int r0 = tid >> 2,        c0 = tid & 3;
    const int r1 = (tid + 256) >> 2, c1 = (tid + 256) & 3;

    const __nv_bfloat16* Abase = A + (size_t)m0 * K;
    const __nv_bfloat16* Wbase = W + (size_t)n0 * K;

    auto prefetch = [&](int stage, int kk) {
        uint32_t sA = sb + stage * STAGE_B;
        uint32_t sB = sA + TILE_B;
        CP_ASYNC16(sA + (uint32_t)(r0 * ROW_H + c0 * 8) * 2,
                   Abase + (size_t)r0 * K + kk + c0 * 8);
        CP_ASYNC16(sA + (uint32_t)(r1 * ROW_H + c1 * 8) * 2,
                   Abase + (size_t)r1 * K + kk + c1 * 8);
        CP_ASYNC16(sB + (uint32_t)(r0 * ROW_H + c0 * 8) * 2,
                   Wbase + (size_t)r0 * K + kk + c0 * 8);
        CP_ASYNC16(sB + (uint32_t)(r1 * ROW_H + c1 * 8) * 2,
                   Wbase + (size_t)r1 * K + kk + c1 * 8);
    };

    float acc[2][8][4];
#pragma unroll
    for (int tm = 0; tm < 2; tm++)
#pragma unroll
        for (int nt = 0; nt < 8; nt++)
#pragma unroll
            for (int j = 0; j < 4; j++) acc[tm][nt][j] = 0.f;

    const int aRowBase = warp_m * 32;
    const int bRowBase = warp_n * 64;
    const int nK = K / BK;

    // prologue: fill STAGES-1 stages
#pragma unroll
    for (int s = 0; s < STAGES - 1; s++) {
        prefetch(s, s * BK);
        CP_COMMIT();
    }

    int cur = 0;
    for (int kt = 0; kt < nK; kt++) {
        CP_WAIT(STAGES - 2);
        __syncthreads();

        // prefetch next stage right away (target stage was consumed at kt-1,
        // guaranteed drained: its frags fed MMAs issued before last barrier)
        if (kt + STAGES - 1 < nK) {
            int wstage = cur + STAGES - 1;
            if (wstage >= STAGES) wstage -= STAGES;
            prefetch(wstage, (kt + STAGES - 1) * BK);
        }
        CP_COMMIT();

        const uint32_t sA = sb + cur * STAGE_B;
        const uint32_t sBm = sA + TILE_B;

        // ---- load fragments ----
        uint32_t af[2][2][4];   // [ks][tm][4]
        uint32_t bf[2][8][2];   // [ks][nt][2]
#pragma unroll
        for (int ks = 0; ks < 2; ks++) {
#pragma unroll
            for (int tm = 0; tm < 2; tm++) {
                int row = aRowBase + tm * 16 + (lid & 15);
                int col = ks * 16 + (lid >> 4) * 8;
                ldsm_x4(af[ks][tm], sA + (uint32_t)(row * ROW_H + col) * 2);
            }
#pragma unroll
            for (int ntp = 0; ntp < 4; ntp++) {
                int g = lid >> 3;
                int row = bRowBase + ntp * 16 + (g >> 1) * 8 + (lid & 7);
                int col = ks * 16 + (g & 1) * 8;
                uint32_t r[4];
                ldsm_x4(r, sBm + (uint32_t)(row * ROW_H + col) * 2);
                bf[ks][2 * ntp][0]     = r[0];
                bf[ks][2 * ntp][1]     = r[1];
                bf[ks][2 * ntp + 1][0] = r[2];
                bf[ks][2 * ntp + 1][1] = r[3];
            }
        }

        // ---- 32 mma per warp per K-substep ----
#pragma unroll
        for (int ks = 0; ks < 2; ks++)
#pragma unroll
            for (int tm = 0; tm < 2; tm++)
#pragma unroll
                for (int nt = 0; nt < 8; nt++)
                    mma_16816(acc[tm][nt], af[ks][tm], bf[ks][nt]);

        if (++cur == STAGES) cur = 0;
    }

    // ---- epilogue: fused bias, float2 stores ----
    const int g = lid >> 2;               // 0..7
    const int tc = (lid & 3) * 2;         // 0,2,4,6
#pragma unroll
    for (int nt = 0; nt < 8; nt++) {
        int col = n0 + warp_n * 64 + nt * 8 + tc;
        float2 bv = *reinterpret_cast<const float2*>(bias + col);
#pragma unroll
        for (int tm = 0; tm < 2; tm++) {
            int row = m0 + warp_m * 32 + tm * 16 + g;
            float2 v0 = { acc[tm][nt][0] + bv.x, acc[tm][nt][1] + bv.y };
            float2 v1 = { acc[tm][nt][2] + bv.x, acc[tm][nt][3] + bv.y };
            *reinterpret_cast<float2*>(out + (size_t)row * N + col) = v0;
            *reinterpret_cast<float2*>(out + (size_t)(row + 8) * N + col) = v1;
        }
    }
}

// ============================================================================
// launch
// ============================================================================
extern "C" void kernel_launch(void* const* d_in, const int* in_sizes, int n_in,
                              void* d_out, int out_size)
{
    const float* inp  = (const float*)d_in[0];   // [B*S, K] fp32
    const float* w    = (const float*)d_in[1];   // [N, K]  fp32
    const float* bias = (const float*)d_in[2];   // [N]     fp32
    float* out = (float*)d_out;

    int N = in_sizes[2];
    int K = in_sizes[1] / N;
    int M = (int)((long long)in_sizes[0] / K);

    __nv_bfloat16 *Aq, *Wq;
    cudaGetSymbolAddress((void**)&Aq, g_Aq);
    cudaGetSymbolAddress((void**)&Wq, g_Wq);

    int aquads = (int)((long long)M * K / 4);
    int wquads = (int)((long long)N * K / 4);
    quant_mxfp4_kernel<<<(aquads + 255) / 256, 256>>>(inp, Aq, aquads);
    quant_mxfp4_kernel<<<(wquads + 255) / 256, 256>>>(w, Wq, wquads);

    static bool attr_set = false;
    if (!attr_set) {
        cudaFuncSetAttribute(mxfp4_gemm_kernel,
                             cudaFuncAttributeMaxDynamicSharedMemorySize,
                             SMEM_TOTAL);
        attr_set = true;
    }

    dim3 grid(N / BN, M / BM);
    mxfp4_gemm_kernel<<<grid, 256, SMEM_TOTAL>>>(Aq, Wq, bias, out, M, N, K);
}